// round 1
// baseline (speedup 1.0000x reference)
#include <cuda_runtime.h>
#include <math.h>

#define N_NODES 100000
#define DIM     128
#define N_REL   8
#define N_EDGES 640000

// ---------------- scratch (static device globals; no allocation) -------------
__device__ float g_deg [N_NODES];
__device__ float g_dinv[N_NODES];
__device__ float g_coef[N_EDGES];
__device__ float g_xW  [(size_t)N_NODES * N_REL * DIM];   // [N, R, D] 409.6 MB
__device__ float g_z1  [(size_t)N_NODES * DIM];
__device__ float g_agg [(size_t)N_NODES * DIM];

// ---------------- degree / normalization ------------------------------------
__global__ void deg_kernel(const int* __restrict__ col) {
    int e = blockIdx.x * blockDim.x + threadIdx.x;
    if (e < N_EDGES) atomicAdd(&g_deg[col[e]], 1.0f);
}

__global__ void dinv_kernel() {
    int n = blockIdx.x * blockDim.x + threadIdx.x;
    if (n < N_NODES) {
        float d = g_deg[n];
        g_dinv[n] = (d > 0.0f) ? rsqrtf(d) : 0.0f;
    }
}

__global__ void coef_kernel(const int* __restrict__ row,
                            const int* __restrict__ col,
                            const float* __restrict__ ew) {
    int e = blockIdx.x * blockDim.x + threadIdx.x;
    if (e < N_EDGES)
        g_coef[e] = g_dinv[row[e]] * g_dinv[col[e]] * ew[e];
}

// ---------------- dense per-relation transform: xW[n,r,:] = A[n,:] @ W_r -----
// Tile 128(m) x 128(n), Ktile=32, 256 threads, 8x8 microtile per thread.
__global__ __launch_bounds__(256)
void gemm_xw_kernel(const float* __restrict__ A,      // [N, 128]
                    const float* __restrict__ W) {    // [8, 128, 128]
    __shared__ float As[128][33];    // [m][k], padded
    __shared__ float Bs[32][128];    // [k][j]

    const int tid = threadIdx.x;
    const int tx  = tid & 15;        // -> 8 output cols: tx*4.. , 64+tx*4..
    const int ty  = tid >> 4;        // -> 8 output rows: ty*4.. , 64+ty*4..
    const int m0  = blockIdx.x * 128;
    const int rel = blockIdx.y;
    const float* Wr = W + (size_t)rel * DIM * DIM;

    float acc[8][8];
    #pragma unroll
    for (int i = 0; i < 8; i++)
        #pragma unroll
        for (int j = 0; j < 8; j++) acc[i][j] = 0.0f;

    for (int k0 = 0; k0 < DIM; k0 += 32) {
        // load A tile: 128 x 32 = 1024 float4
        #pragma unroll
        for (int q = 0; q < 4; q++) {
            int fid = tid + q * 256;          // < 1024
            int m   = fid >> 3;
            int kq  = fid & 7;
            float4 v = make_float4(0.f, 0.f, 0.f, 0.f);
            if (m0 + m < N_NODES)
                v = *(const float4*)&A[(size_t)(m0 + m) * DIM + k0 + kq * 4];
            As[m][kq * 4 + 0] = v.x;
            As[m][kq * 4 + 1] = v.y;
            As[m][kq * 4 + 2] = v.z;
            As[m][kq * 4 + 3] = v.w;
        }
        // load B tile: 32 x 128 = 1024 float4
        #pragma unroll
        for (int q = 0; q < 4; q++) {
            int fid = tid + q * 256;
            int k   = fid >> 5;
            int jq  = fid & 31;
            float4 v = *(const float4*)&Wr[(size_t)(k0 + k) * DIM + jq * 4];
            *(float4*)&Bs[k][jq * 4] = v;
        }
        __syncthreads();

        #pragma unroll 8
        for (int k = 0; k < 32; k++) {
            float a[8], b[8];
            #pragma unroll
            for (int i = 0; i < 4; i++) {
                a[i]     = As[ty * 4 + i][k];
                a[i + 4] = As[64 + ty * 4 + i][k];
            }
            float4 b0 = *(const float4*)&Bs[k][tx * 4];
            float4 b1 = *(const float4*)&Bs[k][64 + tx * 4];
            b[0] = b0.x; b[1] = b0.y; b[2] = b0.z; b[3] = b0.w;
            b[4] = b1.x; b[5] = b1.y; b[6] = b1.z; b[7] = b1.w;
            #pragma unroll
            for (int i = 0; i < 8; i++)
                #pragma unroll
                for (int j = 0; j < 8; j++)
                    acc[i][j] = fmaf(a[i], b[j], acc[i][j]);
        }
        __syncthreads();
    }

    // epilogue: xW[(n*8 + rel)*128 + j]
    #pragma unroll
    for (int i = 0; i < 8; i++) {
        int r_loc = (i < 4) ? (ty * 4 + i) : (64 + ty * 4 + (i - 4));
        int n = m0 + r_loc;
        if (n < N_NODES) {
            size_t base = ((size_t)n * N_REL + rel) * DIM;
            float4 v0 = make_float4(acc[i][0], acc[i][1], acc[i][2], acc[i][3]);
            float4 v1 = make_float4(acc[i][4], acc[i][5], acc[i][6], acc[i][7]);
            *(float4*)&g_xW[base + tx * 4]      = v0;
            *(float4*)&g_xW[base + 64 + tx * 4] = v1;
        }
    }
}

// ---------------- per-edge gather + scatter-add ------------------------------
// One warp per edge: lane handles 4 dims (float4 read, 4 scalar atomics).
__global__ __launch_bounds__(256)
void scatter_kernel(const int* __restrict__ row,
                    const int* __restrict__ col,
                    const int* __restrict__ etype) {
    int idx  = blockIdx.x * 256 + threadIdx.x;
    int e    = idx >> 5;
    int lane = idx & 31;
    if (e >= N_EDGES) return;
    float cf = g_coef[e];
    int r = row[e], c = col[e], t = etype[e];
    const float4* src = (const float4*)&g_xW[((size_t)r * N_REL + t) * DIM];
    float4 v = src[lane];
    float* dst = &g_agg[(size_t)c * DIM + lane * 4];
    atomicAdd(dst + 0, cf * v.x);
    atomicAdd(dst + 1, cf * v.y);
    atomicAdd(dst + 2, cf * v.z);
    atomicAdd(dst + 3, cf * v.w);
}

// ---------------- bias + relu -> z1 ------------------------------------------
__global__ void bias_relu_kernel(const float* __restrict__ b1) {
    int i = blockIdx.x * blockDim.x + threadIdx.x;
    if (i < N_NODES * DIM) {
        float v = g_agg[i] + b1[i & (DIM - 1)];
        g_z1[i] = v > 0.0f ? v : 0.0f;
    }
}

// ---------------- final combine ----------------------------------------------
__global__ void final_kernel(const float* __restrict__ x,
                             const float* __restrict__ b2,
                             float* __restrict__ out) {
    int i = blockIdx.x * blockDim.x + threadIdx.x;
    if (i < N_NODES * DIM) {
        float z2  = g_agg[i] + b2[i & (DIM - 1)];
        float z1v = g_z1[i];
        float xv  = x[i];
        out[i]                         = (xv + z1v + z2) * 0.25f;         // z_star
        out[(size_t)N_NODES * DIM + i] = (z1v + z2) * (1.0f / 3.0f);      // z_sharp (LAMDA=1)
    }
}

// ---------------- launch -----------------------------------------------------
extern "C" void kernel_launch(void* const* d_in, const int* in_sizes, int n_in,
                              void* d_out, int out_size) {
    const float* x  = (const float*)d_in[0];
    const int*   ei = (const int*)  d_in[1];
    const int*   et = (const int*)  d_in[2];
    const float* ew = (const float*)d_in[3];
    const float* W1 = (const float*)d_in[4];
    const float* b1 = (const float*)d_in[5];
    const float* W2 = (const float*)d_in[6];
    const float* b2 = (const float*)d_in[7];
    float* out = (float*)d_out;

    const int* row = ei;
    const int* col = ei + N_EDGES;

    void *p_deg, *p_agg;
    cudaGetSymbolAddress(&p_deg, g_deg);
    cudaGetSymbolAddress(&p_agg, g_agg);

    const int EB = (N_EDGES + 255) / 256;
    const int NB = (N_NODES + 255) / 256;
    const int VB = (N_NODES * DIM + 255) / 256;
    const int SB = (N_EDGES * 32 + 255) / 256;
    dim3 ggrid((N_NODES + 127) / 128, N_REL);

    // normalization coefficients
    cudaMemsetAsync(p_deg, 0, sizeof(float) * N_NODES);
    deg_kernel<<<EB, 256>>>(col);
    dinv_kernel<<<NB, 256>>>();
    coef_kernel<<<EB, 256>>>(row, col, ew);

    // conv 1: z1 = relu(scatter(coef * (x@W1)[row,type], col) + b1)
    cudaMemsetAsync(p_agg, 0, sizeof(float) * N_NODES * DIM);
    gemm_xw_kernel<<<ggrid, 256>>>(x, W1);
    scatter_kernel<<<SB, 256>>>(row, col, et);
    bias_relu_kernel<<<VB, 256>>>(b1);

    // conv 2: z2 = scatter(coef * (z1@W2)[row,type], col) + b2
    cudaMemsetAsync(p_agg, 0, sizeof(float) * N_NODES * DIM);
    // g_z1 lives in device memory; get its address for the GEMM input
    {
        void* p_z1;
        cudaGetSymbolAddress(&p_z1, g_z1);
        gemm_xw_kernel<<<ggrid, 256>>>((const float*)p_z1, W2);
    }
    scatter_kernel<<<SB, 256>>>(row, col, et);

    // combine
    final_kernel<<<VB, 256>>>(x, b2, out);
}

// round 3
// speedup vs baseline: 1.3293x; 1.3293x over previous
#include <cuda_runtime.h>
#include <cuda_bf16.h>
#include <math.h>
#include <stdint.h>

#define N_NODES 100000
#define DIM     128
#define N_REL   8
#define N_EDGES 640000

// ---------------- scratch (static device globals; no allocation) -------------
__device__ float g_deg [N_NODES];
__device__ float g_dinv[N_NODES];
__device__ float g_coef[N_EDGES];
__device__ float g_xW  [(size_t)N_NODES * N_REL * DIM];   // [N, R, D]
__device__ float g_z1  [(size_t)N_NODES * DIM];
__device__ float g_agg [(size_t)N_NODES * DIM];
// prepacked, transposed (W^T: [r][j=out][k=in]) bf16 hi/lo weight images
__device__ uint4 g_B1h[16384];   // 8 rel * 32768 B each
__device__ uint4 g_B1l[16384];
__device__ uint4 g_B2h[16384];
__device__ uint4 g_B2l[16384];

// ===================== helpers ===============================================
__device__ __forceinline__ uint32_t smem_u32(const void* p) {
    uint32_t a;
    asm("{ .reg .u64 t; cvta.to.shared.u64 t, %1; cvt.u32.u64 %0, t; }" : "=r"(a) : "l"(p));
    return a;
}

__device__ __forceinline__ void split4(float4 v, uint2& hi, uint2& lo) {
    __nv_bfloat16 h0 = __float2bfloat16(v.x), h1 = __float2bfloat16(v.y);
    __nv_bfloat16 h2 = __float2bfloat16(v.z), h3 = __float2bfloat16(v.w);
    __nv_bfloat16 l0 = __float2bfloat16(v.x - __bfloat162float(h0));
    __nv_bfloat16 l1 = __float2bfloat16(v.y - __bfloat162float(h1));
    __nv_bfloat16 l2 = __float2bfloat16(v.z - __bfloat162float(h2));
    __nv_bfloat16 l3 = __float2bfloat16(v.w - __bfloat162float(h3));
    hi.x = (uint32_t)__bfloat16_as_ushort(h0) | ((uint32_t)__bfloat16_as_ushort(h1) << 16);
    hi.y = (uint32_t)__bfloat16_as_ushort(h2) | ((uint32_t)__bfloat16_as_ushort(h3) << 16);
    lo.x = (uint32_t)__bfloat16_as_ushort(l0) | ((uint32_t)__bfloat16_as_ushort(l1) << 16);
    lo.y = (uint32_t)__bfloat16_as_ushort(l2) | ((uint32_t)__bfloat16_as_ushort(l3) << 16);
}

#define LDSM_X4(r0, r1, r2, r3, addr) \
    asm volatile("ldmatrix.sync.aligned.m8n8.x4.shared.b16 {%0,%1,%2,%3}, [%4];" \
                 : "=r"(r0), "=r"(r1), "=r"(r2), "=r"(r3) : "r"(addr))

#define MMA16816(c, a0, a1, a2, a3, b0, b1) \
    asm volatile("mma.sync.aligned.m16n8k16.row.col.f32.bf16.bf16.f32 " \
                 "{%0,%1,%2,%3}, {%4,%5,%6,%7}, {%8,%9}, {%0,%1,%2,%3};" \
                 : "+f"((c)[0]), "+f"((c)[1]), "+f"((c)[2]), "+f"((c)[3]) \
                 : "r"(a0), "r"(a1), "r"(a2), "r"(a3), "r"(b0), "r"(b1))

#define CP_ASYNC16(dst, src) \
    asm volatile("cp.async.ca.shared.global [%0], [%1], 16;" :: "r"(dst), "l"(src) : "memory")
#define CP_COMMIT() asm volatile("cp.async.commit_group;" ::: "memory")

// ---------------- weight prepack: transpose + bf16-split ---------------------
// out[r][j][k] = W[r][k][j] as bf16 hi/lo, plain row-major.
__global__ void prepack_kernel(const float* __restrict__ W,
                               unsigned char* __restrict__ outh,
                               unsigned char* __restrict__ outl) {
    int t = blockIdx.x * 256 + threadIdx.x;     // 32768 threads
    if (t >= N_REL * 128 * 32) return;
    int r  = t >> 12;
    int j  = (t >> 5) & 127;
    int k  = (t & 31) * 4;
    const float* Wr = W + r * 16384;
    float4 v = make_float4(Wr[(k + 0) * 128 + j], Wr[(k + 1) * 128 + j],
                           Wr[(k + 2) * 128 + j], Wr[(k + 3) * 128 + j]);
    uint2 hi, lo;
    split4(v, hi, lo);
    uint32_t off = (uint32_t)r * 32768u + (uint32_t)j * 256u + (uint32_t)k * 2u;
    *(uint2*)(outh + off) = hi;
    *(uint2*)(outl + off) = lo;
}

// ---------------- mma.sync relation-transform GEMM ---------------------------
// xW[n, r, :] = A[n, :] @ W_r for all 8 relations. One CTA per 128-node tile.
// SMEM layout (padded stride 136 bf16 = 272 B per row, 16B-aligned rows):
static constexpr int S_ELEM = 136;
static constexpr int S_BYTE = S_ELEM * 2;              // 272
static constexpr int TILE_B = 128 * S_BYTE;            // 34816
static constexpr int OFF_A_HI = 0;
static constexpr int OFF_A_LO = TILE_B;                // 34816
static constexpr int OFF_B    = 2 * TILE_B;            // 69632; stage s at +s*2*TILE_B
static constexpr int SMEM_BYTES = OFF_B + 4 * TILE_B;  // 208896

__global__ __launch_bounds__(256, 1)
void rgemm_kernel(const float* __restrict__ A,
                  const uint4* __restrict__ Bh,
                  const uint4* __restrict__ Bl,
                  float* __restrict__ xW) {
    extern __shared__ unsigned char smem[];
    const uint32_t sb = smem_u32(smem);
    const int tid    = threadIdx.x;
    const int wid    = tid >> 5;
    const int lane   = tid & 31;
    const int warp_m = wid & 3;          // 4 tiles of 32 rows
    const int warp_n = wid >> 2;         // 2 tiles of 64 cols
    const int m0     = blockIdx.x * 128;

    // ---- convert A tile (fp32 -> hi/lo bf16) into padded SMEM --------------
    {
        const int cg = tid & 31;         // col group of 4 elems
        const int w  = tid >> 5;
        #pragma unroll
        for (int i = 0; i < 16; i++) {
            int row = w + i * 8;
            int n   = m0 + row;
            float4 v = make_float4(0.f, 0.f, 0.f, 0.f);
            if (n < N_NODES) v = ((const float4*)A)[(size_t)n * 32 + cg];
            uint2 hi, lo;
            split4(v, hi, lo);
            uint32_t off = (uint32_t)row * S_BYTE + (uint32_t)cg * 8;
            *(uint2*)(smem + OFF_A_HI + off) = hi;
            *(uint2*)(smem + OFF_A_LO + off) = lo;
        }
    }

    // ---- ldmatrix fragment addresses (fixed per thread) --------------------
    const int lr = lane & 15;
    const int lc = lane >> 4;
    uint32_t aRow[2], bRow[4];
    #pragma unroll
    for (int mt = 0; mt < 2; mt++)
        aRow[mt] = (uint32_t)(warp_m * 32 + mt * 16 + lr) * S_BYTE + lc * 16;
    #pragma unroll
    for (int g = 0; g < 4; g++)
        bRow[g] = (uint32_t)(warp_n * 64 + g * 16 + lr) * S_BYTE + lc * 16;

    // ---- B double-buffer loader (cp.async) ---------------------------------
    auto load_B = [&](int r, int s) {
        uint32_t dstH = sb + OFF_B + s * (2 * TILE_B);
        uint32_t dstL = dstH + TILE_B;
        const char* srcH = (const char*)Bh + (size_t)r * 32768;
        const char* srcL = (const char*)Bl + (size_t)r * 32768;
        #pragma unroll
        for (int q = 0; q < 8; q++) {
            int i   = tid + q * 256;       // 0..2047 chunks of 16B
            int j   = i >> 4;
            int k16 = i & 15;
            uint32_t doff = (uint32_t)j * S_BYTE + k16 * 16;
            uint32_t soff = (uint32_t)j * 256 + k16 * 16;
            CP_ASYNC16(dstH + doff, srcH + soff);
            CP_ASYNC16(dstL + doff, srcL + soff);
        }
        CP_COMMIT();
    };

    load_B(0, 0);
    __syncthreads();   // A tile visible to all warps

    for (int r = 0; r < N_REL; r++) {
        const int s = r & 1;
        if (r < N_REL - 1) load_B(r + 1, s ^ 1);
        if (r < N_REL - 1) asm volatile("cp.async.wait_group 1;" ::: "memory");
        else               asm volatile("cp.async.wait_group 0;" ::: "memory");
        __syncthreads();

        float c[2][8][4];
        #pragma unroll
        for (int mt = 0; mt < 2; mt++)
            #pragma unroll
            for (int nt = 0; nt < 8; nt++)
                #pragma unroll
                for (int e = 0; e < 4; e++) c[mt][nt][e] = 0.0f;

        const uint32_t bStage = sb + OFF_B + s * (2 * TILE_B);
        #pragma unroll
        for (int p = 0; p < 3; p++) {
            const uint32_t aBase = sb + ((p == 2) ? OFF_A_LO : OFF_A_HI);
            const uint32_t bBase = bStage + ((p == 1) ? TILE_B : 0);
            #pragma unroll
            for (int ks = 0; ks < 8; ks++) {
                const uint32_t kb = ks * 32;
                uint32_t a[2][4];
                #pragma unroll
                for (int mt = 0; mt < 2; mt++)
                    LDSM_X4(a[mt][0], a[mt][1], a[mt][2], a[mt][3],
                            aBase + aRow[mt] + kb);
                uint32_t b[4][4];
                #pragma unroll
                for (int g = 0; g < 4; g++)
                    LDSM_X4(b[g][0], b[g][1], b[g][2], b[g][3],
                            bBase + bRow[g] + kb);
                #pragma unroll
                for (int mt = 0; mt < 2; mt++)
                    #pragma unroll
                    for (int g = 0; g < 4; g++) {
                        MMA16816(c[mt][g * 2 + 0], a[mt][0], a[mt][1], a[mt][2], a[mt][3],
                                 b[g][0], b[g][2]);
                        MMA16816(c[mt][g * 2 + 1], a[mt][0], a[mt][1], a[mt][2], a[mt][3],
                                 b[g][1], b[g][3]);
                    }
            }
        }

        // ---- epilogue: direct stores to xW[n][r][d] ------------------------
        const int gid = lane >> 2;
        const int tig = lane & 3;
        #pragma unroll
        for (int mt = 0; mt < 2; mt++) {
            int rowA = warp_m * 32 + mt * 16 + gid;
            int nA = m0 + rowA;
            int nB = nA + 8;
            float* baseA = (nA < N_NODES) ? &xW[((size_t)nA * N_REL + r) * DIM] : nullptr;
            float* baseB = (nB < N_NODES) ? &xW[((size_t)nB * N_REL + r) * DIM] : nullptr;
            #pragma unroll
            for (int nt = 0; nt < 8; nt++) {
                int d = warp_n * 64 + nt * 8 + 2 * tig;
                if (baseA) *(float2*)&baseA[d] = make_float2(c[mt][nt][0], c[mt][nt][1]);
                if (baseB) *(float2*)&baseB[d] = make_float2(c[mt][nt][2], c[mt][nt][3]);
            }
        }
        __syncthreads();   // stage s free for next prefetch overwrite
    }
}

// ---------------- degree / normalization ------------------------------------
__global__ void deg_kernel(const int* __restrict__ col) {
    int e = blockIdx.x * blockDim.x + threadIdx.x;
    if (e < N_EDGES) atomicAdd(&g_deg[col[e]], 1.0f);
}

__global__ void dinv_kernel() {
    int n = blockIdx.x * blockDim.x + threadIdx.x;
    if (n < N_NODES) {
        float d = g_deg[n];
        g_dinv[n] = (d > 0.0f) ? rsqrtf(d) : 0.0f;
    }
}

__global__ void coef_kernel(const int* __restrict__ row,
                            const int* __restrict__ col,
                            const float* __restrict__ ew) {
    int e = blockIdx.x * blockDim.x + threadIdx.x;
    if (e < N_EDGES)
        g_coef[e] = g_dinv[row[e]] * g_dinv[col[e]] * ew[e];
}

// ---------------- per-edge gather + scatter-add ------------------------------
__global__ __launch_bounds__(256)
void scatter_kernel(const int* __restrict__ row,
                    const int* __restrict__ col,
                    const int* __restrict__ etype) {
    int idx  = blockIdx.x * 256 + threadIdx.x;
    int e    = idx >> 5;
    int lane = idx & 31;
    if (e >= N_EDGES) return;
    float cf = g_coef[e];
    int r = row[e], c = col[e], t = etype[e];
    const float4* src = (const float4*)&g_xW[((size_t)r * N_REL + t) * DIM];
    float4 v = src[lane];
    float* dst = &g_agg[(size_t)c * DIM + lane * 4];
    atomicAdd(dst + 0, cf * v.x);
    atomicAdd(dst + 1, cf * v.y);
    atomicAdd(dst + 2, cf * v.z);
    atomicAdd(dst + 3, cf * v.w);
}

// ---------------- bias + relu -> z1 ------------------------------------------
__global__ void bias_relu_kernel(const float* __restrict__ b1) {
    int i = blockIdx.x * blockDim.x + threadIdx.x;
    if (i < N_NODES * DIM) {
        float v = g_agg[i] + b1[i & (DIM - 1)];
        g_z1[i] = v > 0.0f ? v : 0.0f;
    }
}

// ---------------- final combine ----------------------------------------------
__global__ void final_kernel(const float* __restrict__ x,
                             const float* __restrict__ b2,
                             float* __restrict__ out) {
    int i = blockIdx.x * blockDim.x + threadIdx.x;
    if (i < N_NODES * DIM) {
        float z2  = g_agg[i] + b2[i & (DIM - 1)];
        float z1v = g_z1[i];
        float xv  = x[i];
        out[i]                         = (xv + z1v + z2) * 0.25f;
        out[(size_t)N_NODES * DIM + i] = (z1v + z2) * (1.0f / 3.0f);
    }
}

// ---------------- launch -----------------------------------------------------
extern "C" void kernel_launch(void* const* d_in, const int* in_sizes, int n_in,
                              void* d_out, int out_size) {
    const float* x  = (const float*)d_in[0];
    const int*   ei = (const int*)  d_in[1];
    const int*   et = (const int*)  d_in[2];
    const float* ew = (const float*)d_in[3];
    const float* W1 = (const float*)d_in[4];
    const float* b1 = (const float*)d_in[5];
    const float* W2 = (const float*)d_in[6];
    const float* b2 = (const float*)d_in[7];
    float* out = (float*)d_out;

    const int* row = ei;
    const int* col = ei + N_EDGES;

    void *p_deg, *p_agg, *p_z1, *p_xW, *p_B1h, *p_B1l, *p_B2h, *p_B2l;
    cudaGetSymbolAddress(&p_deg, g_deg);
    cudaGetSymbolAddress(&p_agg, g_agg);
    cudaGetSymbolAddress(&p_z1,  g_z1);
    cudaGetSymbolAddress(&p_xW,  g_xW);
    cudaGetSymbolAddress(&p_B1h, g_B1h);
    cudaGetSymbolAddress(&p_B1l, g_B1l);
    cudaGetSymbolAddress(&p_B2h, g_B2h);
    cudaGetSymbolAddress(&p_B2l, g_B2l);

    cudaFuncSetAttribute(rgemm_kernel, cudaFuncAttributeMaxDynamicSharedMemorySize, SMEM_BYTES);

    const int EB = (N_EDGES + 255) / 256;
    const int NB = (N_NODES + 255) / 256;
    const int VB = (N_NODES * DIM + 255) / 256;
    const int SB = (N_EDGES * 32 + 255) / 256;
    const int GB = (N_NODES + 127) / 128;   // 782

    // normalization coefficients
    cudaMemsetAsync(p_deg, 0, sizeof(float) * N_NODES);
    deg_kernel<<<EB, 256>>>(col);
    dinv_kernel<<<NB, 256>>>();
    coef_kernel<<<EB, 256>>>(row, col, ew);

    // weight prepack (transpose + bf16 split)
    prepack_kernel<<<128, 256>>>(W1, (unsigned char*)p_B1h, (unsigned char*)p_B1l);
    prepack_kernel<<<128, 256>>>(W2, (unsigned char*)p_B2h, (unsigned char*)p_B2l);

    // conv 1
    cudaMemsetAsync(p_agg, 0, sizeof(float) * N_NODES * DIM);
    rgemm_kernel<<<GB, 256, SMEM_BYTES>>>(x, (const uint4*)p_B1h, (const uint4*)p_B1l,
                                          (float*)p_xW);
    scatter_kernel<<<SB, 256>>>(row, col, et);
    bias_relu_kernel<<<VB, 256>>>(b1);

    // conv 2
    cudaMemsetAsync(p_agg, 0, sizeof(float) * N_NODES * DIM);
    rgemm_kernel<<<GB, 256, SMEM_BYTES>>>((const float*)p_z1, (const uint4*)p_B2h,
                                          (const uint4*)p_B2l, (float*)p_xW);
    scatter_kernel<<<SB, 256>>>(row, col, et);

    // combine
    final_kernel<<<VB, 256>>>(x, b2, out);
}

// round 4
// speedup vs baseline: 1.6326x; 1.2281x over previous
#include <cuda_runtime.h>
#include <cuda_bf16.h>
#include <math.h>
#include <stdint.h>

#define N_NODES 100000
#define DIM     128
#define N_REL   8
#define N_EDGES 640000

// ---------------- scratch (static device globals; no allocation) -------------
__device__ float g_deg [N_NODES];
__device__ float g_dinv[N_NODES];
__device__ float g_coef[N_EDGES];
__device__ float g_xW  [(size_t)N_NODES * N_REL * DIM];   // [N, R, D]
__device__ float g_z1  [(size_t)N_NODES * DIM];
__device__ float g_agg [(size_t)N_NODES * DIM];
// prepacked, transposed (W^T: [r][j=out][k=in]) bf16 hi/lo weight images
__device__ uint4 g_B1h[16384];   // 8 rel * 32768 B each
__device__ uint4 g_B1l[16384];
__device__ uint4 g_B2h[16384];
__device__ uint4 g_B2l[16384];

// ===================== helpers ===============================================
__device__ __forceinline__ uint32_t smem_u32(const void* p) {
    uint32_t a;
    asm("{ .reg .u64 t; cvta.to.shared.u64 t, %1; cvt.u32.u64 %0, t; }" : "=r"(a) : "l"(p));
    return a;
}

__device__ __forceinline__ void split4(float4 v, uint2& hi, uint2& lo) {
    __nv_bfloat16 h0 = __float2bfloat16(v.x), h1 = __float2bfloat16(v.y);
    __nv_bfloat16 h2 = __float2bfloat16(v.z), h3 = __float2bfloat16(v.w);
    __nv_bfloat16 l0 = __float2bfloat16(v.x - __bfloat162float(h0));
    __nv_bfloat16 l1 = __float2bfloat16(v.y - __bfloat162float(h1));
    __nv_bfloat16 l2 = __float2bfloat16(v.z - __bfloat162float(h2));
    __nv_bfloat16 l3 = __float2bfloat16(v.w - __bfloat162float(h3));
    hi.x = (uint32_t)__bfloat16_as_ushort(h0) | ((uint32_t)__bfloat16_as_ushort(h1) << 16);
    hi.y = (uint32_t)__bfloat16_as_ushort(h2) | ((uint32_t)__bfloat16_as_ushort(h3) << 16);
    lo.x = (uint32_t)__bfloat16_as_ushort(l0) | ((uint32_t)__bfloat16_as_ushort(l1) << 16);
    lo.y = (uint32_t)__bfloat16_as_ushort(l2) | ((uint32_t)__bfloat16_as_ushort(l3) << 16);
}

#define LDSM_X4(r0, r1, r2, r3, addr) \
    asm volatile("ldmatrix.sync.aligned.m8n8.x4.shared.b16 {%0,%1,%2,%3}, [%4];" \
                 : "=r"(r0), "=r"(r1), "=r"(r2), "=r"(r3) : "r"(addr))

#define MMA16816(c, a0, a1, a2, a3, b0, b1) \
    asm volatile("mma.sync.aligned.m16n8k16.row.col.f32.bf16.bf16.f32 " \
                 "{%0,%1,%2,%3}, {%4,%5,%6,%7}, {%8,%9}, {%0,%1,%2,%3};" \
                 : "+f"((c)[0]), "+f"((c)[1]), "+f"((c)[2]), "+f"((c)[3]) \
                 : "r"(a0), "r"(a1), "r"(a2), "r"(a3), "r"(b0), "r"(b1))

#define CP_ASYNC16(dst, src) \
    asm volatile("cp.async.ca.shared.global [%0], [%1], 16;" :: "r"(dst), "l"(src) : "memory")
#define CP_COMMIT() asm volatile("cp.async.commit_group;" ::: "memory")

// ---------------- weight prepack: transpose + bf16-split ---------------------
__global__ void prepack_kernel(const float* __restrict__ W,
                               unsigned char* __restrict__ outh,
                               unsigned char* __restrict__ outl) {
    int t = blockIdx.x * 256 + threadIdx.x;     // 32768 threads
    if (t >= N_REL * 128 * 32) return;
    int r  = t >> 12;
    int j  = (t >> 5) & 127;
    int k  = (t & 31) * 4;
    const float* Wr = W + r * 16384;
    float4 v = make_float4(Wr[(k + 0) * 128 + j], Wr[(k + 1) * 128 + j],
                           Wr[(k + 2) * 128 + j], Wr[(k + 3) * 128 + j]);
    uint2 hi, lo;
    split4(v, hi, lo);
    uint32_t off = (uint32_t)r * 32768u + (uint32_t)j * 256u + (uint32_t)k * 2u;
    *(uint2*)(outh + off) = hi;
    *(uint2*)(outl + off) = lo;
}

// ---------------- mma.sync relation-transform GEMM ---------------------------
static constexpr int S_ELEM = 136;
static constexpr int S_BYTE = S_ELEM * 2;              // 272
static constexpr int TILE_B = 128 * S_BYTE;            // 34816
static constexpr int OFF_A_HI = 0;
static constexpr int OFF_A_LO = TILE_B;                // 34816
static constexpr int OFF_B    = 2 * TILE_B;            // 69632; stage s at +s*2*TILE_B
static constexpr int SMEM_BYTES = OFF_B + 4 * TILE_B;  // 208896

__global__ __launch_bounds__(256, 1)
void rgemm_kernel(const float* __restrict__ A,
                  const uint4* __restrict__ Bh,
                  const uint4* __restrict__ Bl,
                  float* __restrict__ xW) {
    extern __shared__ unsigned char smem[];
    const uint32_t sb = smem_u32(smem);
    const int tid    = threadIdx.x;
    const int wid    = tid >> 5;
    const int lane   = tid & 31;
    const int warp_m = wid & 3;          // 4 tiles of 32 rows
    const int warp_n = wid >> 2;         // 2 tiles of 64 cols
    const int m0     = blockIdx.x * 128;

    // ---- convert A tile (fp32 -> hi/lo bf16) into padded SMEM --------------
    {
        const int cg = tid & 31;         // col group of 4 elems
        const int w  = tid >> 5;
        #pragma unroll
        for (int i = 0; i < 16; i++) {
            int row = w + i * 8;
            int n   = m0 + row;
            float4 v = make_float4(0.f, 0.f, 0.f, 0.f);
            if (n < N_NODES) v = ((const float4*)A)[(size_t)n * 32 + cg];
            uint2 hi, lo;
            split4(v, hi, lo);
            uint32_t off = (uint32_t)row * S_BYTE + (uint32_t)cg * 8;
            *(uint2*)(smem + OFF_A_HI + off) = hi;
            *(uint2*)(smem + OFF_A_LO + off) = lo;
        }
    }

    // ---- ldmatrix fragment addresses (fixed per thread) --------------------
    const int lr = lane & 15;
    const int lc = lane >> 4;
    uint32_t aRow[2], bRow[4];
    #pragma unroll
    for (int mt = 0; mt < 2; mt++)
        aRow[mt] = (uint32_t)(warp_m * 32 + mt * 16 + lr) * S_BYTE + lc * 16;
    #pragma unroll
    for (int g = 0; g < 4; g++)
        bRow[g] = (uint32_t)(warp_n * 64 + g * 16 + lr) * S_BYTE + lc * 16;

    // ---- B double-buffer loader (cp.async) ---------------------------------
    auto load_B = [&](int r, int s) {
        uint32_t dstH = sb + OFF_B + s * (2 * TILE_B);
        uint32_t dstL = dstH + TILE_B;
        const char* srcH = (const char*)Bh + (size_t)r * 32768;
        const char* srcL = (const char*)Bl + (size_t)r * 32768;
        #pragma unroll
        for (int q = 0; q < 8; q++) {
            int i   = tid + q * 256;       // 0..2047 chunks of 16B
            int j   = i >> 4;
            int k16 = i & 15;
            uint32_t doff = (uint32_t)j * S_BYTE + k16 * 16;
            uint32_t soff = (uint32_t)j * 256 + k16 * 16;
            CP_ASYNC16(dstH + doff, srcH + soff);
            CP_ASYNC16(dstL + doff, srcL + soff);
        }
        CP_COMMIT();
    };

    load_B(0, 0);
    __syncthreads();   // A tile visible to all warps

    for (int r = 0; r < N_REL; r++) {
        const int s = r & 1;
        if (r < N_REL - 1) load_B(r + 1, s ^ 1);
        if (r < N_REL - 1) asm volatile("cp.async.wait_group 1;" ::: "memory");
        else               asm volatile("cp.async.wait_group 0;" ::: "memory");
        __syncthreads();

        float c[2][8][4];
        #pragma unroll
        for (int mt = 0; mt < 2; mt++)
            #pragma unroll
            for (int nt = 0; nt < 8; nt++)
                #pragma unroll
                for (int e = 0; e < 4; e++) c[mt][nt][e] = 0.0f;

        const uint32_t bStageH = sb + OFF_B + s * (2 * TILE_B);
        const uint32_t bStageL = bStageH + TILE_B;
        const uint32_t aBaseH  = sb + OFF_A_HI;
        const uint32_t aBaseL  = sb + OFF_A_LO;

        // one fragment load per k-step, shared across the 3 split passes:
        //   c += Ah@Bh + Ah@Bl + Al@Bh   (Al@Bl dropped, ~2^-18 relative)
        #pragma unroll
        for (int ks = 0; ks < 8; ks++) {
            const uint32_t kb = ks * 32;
            uint32_t ah[2][4], al[2][4];
            #pragma unroll
            for (int mt = 0; mt < 2; mt++) {
                LDSM_X4(ah[mt][0], ah[mt][1], ah[mt][2], ah[mt][3], aBaseH + aRow[mt] + kb);
                LDSM_X4(al[mt][0], al[mt][1], al[mt][2], al[mt][3], aBaseL + aRow[mt] + kb);
            }
            uint32_t bh[4][4], bl[4][4];
            #pragma unroll
            for (int g = 0; g < 4; g++) {
                LDSM_X4(bh[g][0], bh[g][1], bh[g][2], bh[g][3], bStageH + bRow[g] + kb);
                LDSM_X4(bl[g][0], bl[g][1], bl[g][2], bl[g][3], bStageL + bRow[g] + kb);
            }
            #pragma unroll
            for (int mt = 0; mt < 2; mt++)
                #pragma unroll
                for (int g = 0; g < 4; g++) {
                    MMA16816(c[mt][g * 2 + 0], ah[mt][0], ah[mt][1], ah[mt][2], ah[mt][3],
                             bh[g][0], bh[g][2]);
                    MMA16816(c[mt][g * 2 + 1], ah[mt][0], ah[mt][1], ah[mt][2], ah[mt][3],
                             bh[g][1], bh[g][3]);
                    MMA16816(c[mt][g * 2 + 0], ah[mt][0], ah[mt][1], ah[mt][2], ah[mt][3],
                             bl[g][0], bl[g][2]);
                    MMA16816(c[mt][g * 2 + 1], ah[mt][0], ah[mt][1], ah[mt][2], ah[mt][3],
                             bl[g][1], bl[g][3]);
                    MMA16816(c[mt][g * 2 + 0], al[mt][0], al[mt][1], al[mt][2], al[mt][3],
                             bh[g][0], bh[g][2]);
                    MMA16816(c[mt][g * 2 + 1], al[mt][0], al[mt][1], al[mt][2], al[mt][3],
                             bh[g][1], bh[g][3]);
                }
        }

        // ---- epilogue: direct stores to xW[n][r][d] ------------------------
        const int gid = lane >> 2;
        const int tig = lane & 3;
        #pragma unroll
        for (int mt = 0; mt < 2; mt++) {
            int rowA = warp_m * 32 + mt * 16 + gid;
            int nA = m0 + rowA;
            int nB = nA + 8;
            float* baseA = (nA < N_NODES) ? &xW[((size_t)nA * N_REL + r) * DIM] : nullptr;
            float* baseB = (nB < N_NODES) ? &xW[((size_t)nB * N_REL + r) * DIM] : nullptr;
            #pragma unroll
            for (int nt = 0; nt < 8; nt++) {
                int d = warp_n * 64 + nt * 8 + 2 * tig;
                if (baseA) *(float2*)&baseA[d] = make_float2(c[mt][nt][0], c[mt][nt][1]);
                if (baseB) *(float2*)&baseB[d] = make_float2(c[mt][nt][2], c[mt][nt][3]);
            }
        }
        __syncthreads();   // stage s free for next prefetch overwrite
    }
}

// ---------------- degree / normalization ------------------------------------
__global__ void deg_kernel(const int* __restrict__ col) {
    int e = blockIdx.x * blockDim.x + threadIdx.x;
    if (e < N_EDGES) atomicAdd(&g_deg[col[e]], 1.0f);
}

__global__ void dinv_kernel() {
    int n = blockIdx.x * blockDim.x + threadIdx.x;
    if (n < N_NODES) {
        float d = g_deg[n];
        g_dinv[n] = (d > 0.0f) ? rsqrtf(d) : 0.0f;
    }
}

__global__ void coef_kernel(const int* __restrict__ row,
                            const int* __restrict__ col,
                            const float* __restrict__ ew) {
    int e = blockIdx.x * blockDim.x + threadIdx.x;
    if (e < N_EDGES)
        g_coef[e] = g_dinv[row[e]] * g_dinv[col[e]] * ew[e];
}

// ---------------- per-edge gather + scatter-add (vector RED) -----------------
__global__ __launch_bounds__(256)
void scatter_kernel(const int* __restrict__ row,
                    const int* __restrict__ col,
                    const int* __restrict__ etype) {
    int idx  = blockIdx.x * 256 + threadIdx.x;
    int e    = idx >> 5;
    int lane = idx & 31;
    if (e >= N_EDGES) return;
    float cf = g_coef[e];
    int r = row[e], c = col[e], t = etype[e];
    const float4* src = (const float4*)&g_xW[((size_t)r * N_REL + t) * DIM];
    float4 v = src[lane];
    float* dst = &g_agg[(size_t)c * DIM + lane * 4];
    asm volatile("red.global.add.v4.f32 [%0], {%1, %2, %3, %4};"
                 :: "l"(dst), "f"(cf * v.x), "f"(cf * v.y), "f"(cf * v.z), "f"(cf * v.w)
                 : "memory");
}

// ---------------- bias + relu -> z1 (vectorized) ------------------------------
__global__ void bias_relu_kernel(const float* __restrict__ b1) {
    int i = blockIdx.x * blockDim.x + threadIdx.x;       // float4 index
    if (i < N_NODES * DIM / 4) {
        float4 a = ((const float4*)g_agg)[i];
        const float4 b = ((const float4*)b1)[i & 31];
        float4 o;
        o.x = fmaxf(a.x + b.x, 0.f);
        o.y = fmaxf(a.y + b.y, 0.f);
        o.z = fmaxf(a.z + b.z, 0.f);
        o.w = fmaxf(a.w + b.w, 0.f);
        ((float4*)g_z1)[i] = o;
    }
}

// ---------------- final combine (vectorized) ----------------------------------
__global__ void final_kernel(const float* __restrict__ x,
                             const float* __restrict__ b2,
                             float* __restrict__ out) {
    int i = blockIdx.x * blockDim.x + threadIdx.x;       // float4 index
    if (i < N_NODES * DIM / 4) {
        float4 a  = ((const float4*)g_agg)[i];
        float4 b  = ((const float4*)b2)[i & 31];
        float4 z1 = ((const float4*)g_z1)[i];
        float4 xv = ((const float4*)x)[i];
        float4 st, sh;
        st.x = (xv.x + z1.x + a.x + b.x) * 0.25f;  sh.x = (z1.x + a.x + b.x) * (1.f / 3.f);
        st.y = (xv.y + z1.y + a.y + b.y) * 0.25f;  sh.y = (z1.y + a.y + b.y) * (1.f / 3.f);
        st.z = (xv.z + z1.z + a.z + b.z) * 0.25f;  sh.z = (z1.z + a.z + b.z) * (1.f / 3.f);
        st.w = (xv.w + z1.w + a.w + b.w) * 0.25f;  sh.w = (z1.w + a.w + b.w) * (1.f / 3.f);
        ((float4*)out)[i] = st;
        ((float4*)out)[(size_t)N_NODES * DIM / 4 + i] = sh;
    }
}

// ---------------- launch -----------------------------------------------------
extern "C" void kernel_launch(void* const* d_in, const int* in_sizes, int n_in,
                              void* d_out, int out_size) {
    const float* x  = (const float*)d_in[0];
    const int*   ei = (const int*)  d_in[1];
    const int*   et = (const int*)  d_in[2];
    const float* ew = (const float*)d_in[3];
    const float* W1 = (const float*)d_in[4];
    const float* b1 = (const float*)d_in[5];
    const float* W2 = (const float*)d_in[6];
    const float* b2 = (const float*)d_in[7];
    float* out = (float*)d_out;

    const int* row = ei;
    const int* col = ei + N_EDGES;

    void *p_deg, *p_agg, *p_z1, *p_xW, *p_B1h, *p_B1l, *p_B2h, *p_B2l;
    cudaGetSymbolAddress(&p_deg, g_deg);
    cudaGetSymbolAddress(&p_agg, g_agg);
    cudaGetSymbolAddress(&p_z1,  g_z1);
    cudaGetSymbolAddress(&p_xW,  g_xW);
    cudaGetSymbolAddress(&p_B1h, g_B1h);
    cudaGetSymbolAddress(&p_B1l, g_B1l);
    cudaGetSymbolAddress(&p_B2h, g_B2h);
    cudaGetSymbolAddress(&p_B2l, g_B2l);

    cudaFuncSetAttribute(rgemm_kernel, cudaFuncAttributeMaxDynamicSharedMemorySize, SMEM_BYTES);

    const int EB = (N_EDGES + 255) / 256;
    const int NB = (N_NODES + 255) / 256;
    const int V4 = (N_NODES * DIM / 4 + 255) / 256;
    const int SB = (N_EDGES * 32 + 255) / 256;
    const int GB = (N_NODES + 127) / 128;   // 782

    // normalization coefficients
    cudaMemsetAsync(p_deg, 0, sizeof(float) * N_NODES);
    deg_kernel<<<EB, 256>>>(col);
    dinv_kernel<<<NB, 256>>>();
    coef_kernel<<<EB, 256>>>(row, col, ew);

    // weight prepack (transpose + bf16 split)
    prepack_kernel<<<128, 256>>>(W1, (unsigned char*)p_B1h, (unsigned char*)p_B1l);
    prepack_kernel<<<128, 256>>>(W2, (unsigned char*)p_B2h, (unsigned char*)p_B2l);

    // conv 1
    cudaMemsetAsync(p_agg, 0, sizeof(float) * N_NODES * DIM);
    rgemm_kernel<<<GB, 256, SMEM_BYTES>>>(x, (const uint4*)p_B1h, (const uint4*)p_B1l,
                                          (float*)p_xW);
    scatter_kernel<<<SB, 256>>>(row, col, et);
    bias_relu_kernel<<<V4, 256>>>(b1);

    // conv 2
    cudaMemsetAsync(p_agg, 0, sizeof(float) * N_NODES * DIM);
    rgemm_kernel<<<GB, 256, SMEM_BYTES>>>((const float*)p_z1, (const uint4*)p_B2h,
                                          (const uint4*)p_B2l, (float*)p_xW);
    scatter_kernel<<<SB, 256>>>(row, col, et);

    // combine
    final_kernel<<<V4, 256>>>(x, b2, out);
}

// round 5
// speedup vs baseline: 1.6896x; 1.0349x over previous
#include <cuda_runtime.h>
#include <cuda_bf16.h>
#include <math.h>
#include <stdint.h>

#define N_NODES 100000
#define DIM     128
#define N_REL   8
#define N_EDGES 640000

// ---------------- scratch (static device globals; no allocation) -------------
__device__ float g_deg [N_NODES];
__device__ float g_dinv[N_NODES];
__device__ float g_coef[N_EDGES];
__device__ float g_xW  [(size_t)N_NODES * N_REL * DIM];   // [N, R, D]
__device__ float g_z1  [(size_t)N_NODES * DIM];
__device__ float g_agg [(size_t)N_NODES * DIM];
// prepacked, transposed (W^T: [r][j=out][k=in]) bf16 hi/lo weight images
__device__ uint4 g_B1h[16384];   // 8 rel * 32768 B each
__device__ uint4 g_B1l[16384];
__device__ uint4 g_B2h[16384];
__device__ uint4 g_B2l[16384];

// ===================== helpers ===============================================
__device__ __forceinline__ uint32_t smem_u32(const void* p) {
    uint32_t a;
    asm("{ .reg .u64 t; cvta.to.shared.u64 t, %1; cvt.u32.u64 %0, t; }" : "=r"(a) : "l"(p));
    return a;
}

__device__ __forceinline__ void split4(float4 v, uint2& hi, uint2& lo) {
    __nv_bfloat16 h0 = __float2bfloat16(v.x), h1 = __float2bfloat16(v.y);
    __nv_bfloat16 h2 = __float2bfloat16(v.z), h3 = __float2bfloat16(v.w);
    __nv_bfloat16 l0 = __float2bfloat16(v.x - __bfloat162float(h0));
    __nv_bfloat16 l1 = __float2bfloat16(v.y - __bfloat162float(h1));
    __nv_bfloat16 l2 = __float2bfloat16(v.z - __bfloat162float(h2));
    __nv_bfloat16 l3 = __float2bfloat16(v.w - __bfloat162float(h3));
    hi.x = (uint32_t)__bfloat16_as_ushort(h0) | ((uint32_t)__bfloat16_as_ushort(h1) << 16);
    hi.y = (uint32_t)__bfloat16_as_ushort(h2) | ((uint32_t)__bfloat16_as_ushort(h3) << 16);
    lo.x = (uint32_t)__bfloat16_as_ushort(l0) | ((uint32_t)__bfloat16_as_ushort(l1) << 16);
    lo.y = (uint32_t)__bfloat16_as_ushort(l2) | ((uint32_t)__bfloat16_as_ushort(l3) << 16);
}

#define LDSM_X4(r0, r1, r2, r3, addr) \
    asm volatile("ldmatrix.sync.aligned.m8n8.x4.shared.b16 {%0,%1,%2,%3}, [%4];" \
                 : "=r"(r0), "=r"(r1), "=r"(r2), "=r"(r3) : "r"(addr))

#define MMA16816(c, a0, a1, a2, a3, b0, b1) \
    asm volatile("mma.sync.aligned.m16n8k16.row.col.f32.bf16.bf16.f32 " \
                 "{%0,%1,%2,%3}, {%4,%5,%6,%7}, {%8,%9}, {%0,%1,%2,%3};" \
                 : "+f"((c)[0]), "+f"((c)[1]), "+f"((c)[2]), "+f"((c)[3]) \
                 : "r"(a0), "r"(a1), "r"(a2), "r"(a3), "r"(b0), "r"(b1))

#define CP_ASYNC16(dst, src) \
    asm volatile("cp.async.ca.shared.global [%0], [%1], 16;" :: "r"(dst), "l"(src) : "memory")
#define CP_COMMIT() asm volatile("cp.async.commit_group;" ::: "memory")

// ---------------- zero kernels (replace memsets; deterministic launch count) -
__global__ void zero_deg_agg_kernel() {
    int i = blockIdx.x * 256 + threadIdx.x;
    float4 z = make_float4(0.f, 0.f, 0.f, 0.f);
    if (i < N_NODES * DIM / 4)                       ((float4*)g_agg)[i] = z;
    else if (i < N_NODES * DIM / 4 + N_NODES / 4)    ((float4*)g_deg)[i - N_NODES * DIM / 4] = z;
}

__global__ void zero_agg_kernel() {
    int i = blockIdx.x * 256 + threadIdx.x;
    if (i < N_NODES * DIM / 4)
        ((float4*)g_agg)[i] = make_float4(0.f, 0.f, 0.f, 0.f);
}

// ---------------- weight prepack: transpose + bf16-split ---------------------
__global__ void prepack_kernel(const float* __restrict__ W,
                               unsigned char* __restrict__ outh,
                               unsigned char* __restrict__ outl) {
    int t = blockIdx.x * 256 + threadIdx.x;     // 32768 threads
    if (t >= N_REL * 128 * 32) return;
    int r  = t >> 12;
    int j  = (t >> 5) & 127;
    int k  = (t & 31) * 4;
    const float* Wr = W + r * 16384;
    float4 v = make_float4(Wr[(k + 0) * 128 + j], Wr[(k + 1) * 128 + j],
                           Wr[(k + 2) * 128 + j], Wr[(k + 3) * 128 + j]);
    uint2 hi, lo;
    split4(v, hi, lo);
    uint32_t off = (uint32_t)r * 32768u + (uint32_t)j * 256u + (uint32_t)k * 2u;
    *(uint2*)(outh + off) = hi;
    *(uint2*)(outl + off) = lo;
}

// ---------------- mma.sync relation-transform GEMM ---------------------------
static constexpr int S_ELEM = 136;
static constexpr int S_BYTE = S_ELEM * 2;              // 272
static constexpr int TILE_B = 128 * S_BYTE;            // 34816
static constexpr int OFF_A_HI = 0;
static constexpr int OFF_A_LO = TILE_B;                // 34816
static constexpr int OFF_B    = 2 * TILE_B;            // 69632; stage s at +s*2*TILE_B
static constexpr int SMEM_BYTES = OFF_B + 4 * TILE_B;  // 208896

__global__ __launch_bounds__(512, 1)
void rgemm_kernel(const float* __restrict__ A,
                  const uint4* __restrict__ Bh,
                  const uint4* __restrict__ Bl,
                  float* __restrict__ xW) {
    extern __shared__ unsigned char smem[];
    const uint32_t sb = smem_u32(smem);
    const int tid    = threadIdx.x;
    const int wid    = tid >> 5;
    const int lane   = tid & 31;
    const int warp_m = wid & 3;          // 4 tiles of 32 rows
    const int warp_n = wid >> 2;         // 4 tiles of 32 cols
    const int m0     = blockIdx.x * 128;

    // ---- convert A tile (fp32 -> hi/lo bf16) into padded SMEM --------------
    {
        const int cg = tid & 31;         // col group of 4 elems
        const int w  = tid >> 5;         // 0..15
        #pragma unroll
        for (int i = 0; i < 8; i++) {
            int row = w + i * 16;
            int n   = m0 + row;
            float4 v = make_float4(0.f, 0.f, 0.f, 0.f);
            if (n < N_NODES) v = ((const float4*)A)[(size_t)n * 32 + cg];
            uint2 hi, lo;
            split4(v, hi, lo);
            uint32_t off = (uint32_t)row * S_BYTE + (uint32_t)cg * 8;
            *(uint2*)(smem + OFF_A_HI + off) = hi;
            *(uint2*)(smem + OFF_A_LO + off) = lo;
        }
    }

    // ---- ldmatrix fragment addresses (fixed per thread) --------------------
    const int lr = lane & 15;
    const int lc = lane >> 4;
    uint32_t aRow[2], bRow[2];
    #pragma unroll
    for (int mt = 0; mt < 2; mt++)
        aRow[mt] = (uint32_t)(warp_m * 32 + mt * 16 + lr) * S_BYTE + lc * 16;
    #pragma unroll
    for (int g = 0; g < 2; g++)
        bRow[g] = (uint32_t)(warp_n * 32 + g * 16 + lr) * S_BYTE + lc * 16;

    // ---- B double-buffer loader (cp.async, 512 threads) --------------------
    auto load_B = [&](int r, int s) {
        uint32_t dstH = sb + OFF_B + s * (2 * TILE_B);
        uint32_t dstL = dstH + TILE_B;
        const char* srcH = (const char*)Bh + (size_t)r * 32768;
        const char* srcL = (const char*)Bl + (size_t)r * 32768;
        #pragma unroll
        for (int q = 0; q < 4; q++) {
            int i   = tid + q * 512;       // 0..2047 chunks of 16B
            int j   = i >> 4;
            int k16 = i & 15;
            uint32_t doff = (uint32_t)j * S_BYTE + k16 * 16;
            uint32_t soff = (uint32_t)j * 256 + k16 * 16;
            CP_ASYNC16(dstH + doff, srcH + soff);
            CP_ASYNC16(dstL + doff, srcL + soff);
        }
        CP_COMMIT();
    };

    load_B(0, 0);
    __syncthreads();   // A tile visible to all warps

    for (int r = 0; r < N_REL; r++) {
        const int s = r & 1;
        if (r < N_REL - 1) load_B(r + 1, s ^ 1);
        if (r < N_REL - 1) asm volatile("cp.async.wait_group 1;" ::: "memory");
        else               asm volatile("cp.async.wait_group 0;" ::: "memory");
        __syncthreads();

        float c[2][4][4];
        #pragma unroll
        for (int mt = 0; mt < 2; mt++)
            #pragma unroll
            for (int nt = 0; nt < 4; nt++)
                #pragma unroll
                for (int e = 0; e < 4; e++) c[mt][nt][e] = 0.0f;

        const uint32_t bStageH = sb + OFF_B + s * (2 * TILE_B);
        const uint32_t bStageL = bStageH + TILE_B;
        const uint32_t aBaseH  = sb + OFF_A_HI;
        const uint32_t aBaseL  = sb + OFF_A_LO;

        // fragment double-buffer across k-steps
        uint32_t ah[2][2][4], al[2][2][4], bh[2][2][4], bl[2][2][4];

        #define LOAD_FRAG(buf, kb)                                                   \
            do {                                                                     \
                _Pragma("unroll")                                                    \
                for (int mt = 0; mt < 2; mt++) {                                     \
                    LDSM_X4(ah[buf][mt][0], ah[buf][mt][1], ah[buf][mt][2],          \
                            ah[buf][mt][3], aBaseH + aRow[mt] + (kb));               \
                    LDSM_X4(al[buf][mt][0], al[buf][mt][1], al[buf][mt][2],          \
                            al[buf][mt][3], aBaseL + aRow[mt] + (kb));               \
                }                                                                    \
                _Pragma("unroll")                                                    \
                for (int g = 0; g < 2; g++) {                                        \
                    LDSM_X4(bh[buf][g][0], bh[buf][g][1], bh[buf][g][2],             \
                            bh[buf][g][3], bStageH + bRow[g] + (kb));                \
                    LDSM_X4(bl[buf][g][0], bl[buf][g][1], bl[buf][g][2],             \
                            bl[buf][g][3], bStageL + bRow[g] + (kb));                \
                }                                                                    \
            } while (0)

        LOAD_FRAG(0, 0);
        #pragma unroll
        for (int ks = 0; ks < 8; ks++) {
            const int cur = ks & 1;
            if (ks < 7) LOAD_FRAG(cur ^ 1, (ks + 1) * 32);
            // c += Ah@Bh + Ah@Bl + Al@Bh (Al@Bl dropped, ~2^-18 relative)
            #pragma unroll
            for (int mt = 0; mt < 2; mt++)
                #pragma unroll
                for (int g = 0; g < 2; g++) {
                    MMA16816(c[mt][g * 2 + 0], ah[cur][mt][0], ah[cur][mt][1],
                             ah[cur][mt][2], ah[cur][mt][3], bh[cur][g][0], bh[cur][g][2]);
                    MMA16816(c[mt][g * 2 + 1], ah[cur][mt][0], ah[cur][mt][1],
                             ah[cur][mt][2], ah[cur][mt][3], bh[cur][g][1], bh[cur][g][3]);
                    MMA16816(c[mt][g * 2 + 0], ah[cur][mt][0], ah[cur][mt][1],
                             ah[cur][mt][2], ah[cur][mt][3], bl[cur][g][0], bl[cur][g][2]);
                    MMA16816(c[mt][g * 2 + 1], ah[cur][mt][0], ah[cur][mt][1],
                             ah[cur][mt][2], ah[cur][mt][3], bl[cur][g][1], bl[cur][g][3]);
                    MMA16816(c[mt][g * 2 + 0], al[cur][mt][0], al[cur][mt][1],
                             al[cur][mt][2], al[cur][mt][3], bh[cur][g][0], bh[cur][g][2]);
                    MMA16816(c[mt][g * 2 + 1], al[cur][mt][0], al[cur][mt][1],
                             al[cur][mt][2], al[cur][mt][3], bh[cur][g][1], bh[cur][g][3]);
                }
        }
        #undef LOAD_FRAG

        // ---- epilogue: direct stores to xW[n][r][d] ------------------------
        const int gid = lane >> 2;
        const int tig = lane & 3;
        #pragma unroll
        for (int mt = 0; mt < 2; mt++) {
            int rowA = warp_m * 32 + mt * 16 + gid;
            int nA = m0 + rowA;
            int nB = nA + 8;
            float* baseA = (nA < N_NODES) ? &xW[((size_t)nA * N_REL + r) * DIM] : nullptr;
            float* baseB = (nB < N_NODES) ? &xW[((size_t)nB * N_REL + r) * DIM] : nullptr;
            #pragma unroll
            for (int nt = 0; nt < 4; nt++) {
                int d = warp_n * 32 + nt * 8 + 2 * tig;
                if (baseA) *(float2*)&baseA[d] = make_float2(c[mt][nt][0], c[mt][nt][1]);
                if (baseB) *(float2*)&baseB[d] = make_float2(c[mt][nt][2], c[mt][nt][3]);
            }
        }
        __syncthreads();   // stage s free for next prefetch overwrite
    }
}

// ---------------- degree / normalization ------------------------------------
__global__ void deg_kernel(const int* __restrict__ col) {
    int e = blockIdx.x * blockDim.x + threadIdx.x;
    if (e < N_EDGES) atomicAdd(&g_deg[col[e]], 1.0f);
}

__global__ void dinv_kernel() {
    int n = blockIdx.x * blockDim.x + threadIdx.x;
    if (n < N_NODES) {
        float d = g_deg[n];
        g_dinv[n] = (d > 0.0f) ? rsqrtf(d) : 0.0f;
    }
}

__global__ void coef_kernel(const int* __restrict__ row,
                            const int* __restrict__ col,
                            const float* __restrict__ ew) {
    int e = blockIdx.x * blockDim.x + threadIdx.x;
    if (e < N_EDGES)
        g_coef[e] = g_dinv[row[e]] * g_dinv[col[e]] * ew[e];
}

// ---------------- per-edge gather + scatter-add (vector RED) -----------------
__global__ __launch_bounds__(256)
void scatter_kernel(const int* __restrict__ row,
                    const int* __restrict__ col,
                    const int* __restrict__ etype) {
    int idx  = blockIdx.x * 256 + threadIdx.x;
    int e    = idx >> 5;
    int lane = idx & 31;
    if (e >= N_EDGES) return;
    float cf = g_coef[e];
    int r = row[e], c = col[e], t = etype[e];
    const float4* src = (const float4*)&g_xW[((size_t)r * N_REL + t) * DIM];
    float4 v = src[lane];
    float* dst = &g_agg[(size_t)c * DIM + lane * 4];
    asm volatile("red.global.add.v4.f32 [%0], {%1, %2, %3, %4};"
                 :: "l"(dst), "f"(cf * v.x), "f"(cf * v.y), "f"(cf * v.z), "f"(cf * v.w)
                 : "memory");
}

// ---------------- bias + relu -> z1 (vectorized) ------------------------------
__global__ void bias_relu_kernel(const float* __restrict__ b1) {
    int i = blockIdx.x * blockDim.x + threadIdx.x;       // float4 index
    if (i < N_NODES * DIM / 4) {
        float4 a = ((const float4*)g_agg)[i];
        const float4 b = ((const float4*)b1)[i & 31];
        float4 o;
        o.x = fmaxf(a.x + b.x, 0.f);
        o.y = fmaxf(a.y + b.y, 0.f);
        o.z = fmaxf(a.z + b.z, 0.f);
        o.w = fmaxf(a.w + b.w, 0.f);
        ((float4*)g_z1)[i] = o;
    }
}

// ---------------- final combine (vectorized) ----------------------------------
__global__ void final_kernel(const float* __restrict__ x,
                             const float* __restrict__ b2,
                             float* __restrict__ out) {
    int i = blockIdx.x * blockDim.x + threadIdx.x;       // float4 index
    if (i < N_NODES * DIM / 4) {
        float4 a  = ((const float4*)g_agg)[i];
        float4 b  = ((const float4*)b2)[i & 31];
        float4 z1 = ((const float4*)g_z1)[i];
        float4 xv = ((const float4*)x)[i];
        float4 st, sh;
        st.x = (xv.x + z1.x + a.x + b.x) * 0.25f;  sh.x = (z1.x + a.x + b.x) * (1.f / 3.f);
        st.y = (xv.y + z1.y + a.y + b.y) * 0.25f;  sh.y = (z1.y + a.y + b.y) * (1.f / 3.f);
        st.z = (xv.z + z1.z + a.z + b.z) * 0.25f;  sh.z = (z1.z + a.z + b.z) * (1.f / 3.f);
        st.w = (xv.w + z1.w + a.w + b.w) * 0.25f;  sh.w = (z1.w + a.w + b.w) * (1.f / 3.f);
        ((float4*)out)[i] = st;
        ((float4*)out)[(size_t)N_NODES * DIM / 4 + i] = sh;
    }
}

// ---------------- launch -----------------------------------------------------
extern "C" void kernel_launch(void* const* d_in, const int* in_sizes, int n_in,
                              void* d_out, int out_size) {
    const float* x  = (const float*)d_in[0];
    const int*   ei = (const int*)  d_in[1];
    const int*   et = (const int*)  d_in[2];
    const float* ew = (const float*)d_in[3];
    const float* W1 = (const float*)d_in[4];
    const float* b1 = (const float*)d_in[5];
    const float* W2 = (const float*)d_in[6];
    const float* b2 = (const float*)d_in[7];
    float* out = (float*)d_out;

    const int* row = ei;
    const int* col = ei + N_EDGES;

    void *p_z1, *p_xW, *p_B1h, *p_B1l, *p_B2h, *p_B2l;
    cudaGetSymbolAddress(&p_z1,  g_z1);
    cudaGetSymbolAddress(&p_xW,  g_xW);
    cudaGetSymbolAddress(&p_B1h, g_B1h);
    cudaGetSymbolAddress(&p_B1l, g_B1l);
    cudaGetSymbolAddress(&p_B2h, g_B2h);
    cudaGetSymbolAddress(&p_B2l, g_B2l);

    cudaFuncSetAttribute(rgemm_kernel, cudaFuncAttributeMaxDynamicSharedMemorySize, SMEM_BYTES);

    const int EB = (N_EDGES + 255) / 256;
    const int NB = (N_NODES + 255) / 256;
    const int V4 = (N_NODES * DIM / 4 + 255) / 256;
    const int Z1 = (N_NODES * DIM / 4 + N_NODES / 4 + 255) / 256;
    const int SB = (N_EDGES * 32 + 255) / 256;
    const int GB = (N_NODES + 127) / 128;   // 782

    // [0..4] prologue — exactly 5 launches so rgemm1 is ncu's captured launch
    zero_deg_agg_kernel<<<Z1, 256>>>();                                   // [0]
    deg_kernel<<<EB, 256>>>(col);                                         // [1]
    dinv_kernel<<<NB, 256>>>();                                           // [2]
    coef_kernel<<<EB, 256>>>(row, col, ew);                               // [3]
    prepack_kernel<<<128, 256>>>(W1, (unsigned char*)p_B1h,
                                 (unsigned char*)p_B1l);                  // [4]

    // conv 1
    rgemm_kernel<<<GB, 512, SMEM_BYTES>>>(x, (const uint4*)p_B1h,
                                          (const uint4*)p_B1l, (float*)p_xW);  // [5] <- ncu
    scatter_kernel<<<SB, 256>>>(row, col, et);                            // [6]
    bias_relu_kernel<<<V4, 256>>>(b1);                                    // [7]

    // conv 2
    prepack_kernel<<<128, 256>>>(W2, (unsigned char*)p_B2h,
                                 (unsigned char*)p_B2l);                  // [8]
    zero_agg_kernel<<<V4, 256>>>();                                       // [9]
    rgemm_kernel<<<GB, 512, SMEM_BYTES>>>((const float*)p_z1, (const uint4*)p_B2h,
                                          (const uint4*)p_B2l, (float*)p_xW);  // [10]
    scatter_kernel<<<SB, 256>>>(row, col, et);                            // [11]

    // combine
    final_kernel<<<V4, 256>>>(x, b2, out);                                // [12]
}